// round 1
// baseline (speedup 1.0000x reference)
#include <cuda_runtime.h>

#define NN  80           // N (row length)
#define TPB 224          // threads per block = rows per block
#define SS  227          // smem stride: 227 % 32 == 3 (odd, conflict-free in all phases)

// dynamic smem layout (floats):
//   aBuf [NN*SS] : a[j] per row (transposed: [j*SS + rowLocal])
//   phiR [NN*SS] : phi_rev real -> overwritten with num real
//   phiI [NN*SS] : phi_rev imag -> overwritten with num imag
//   dsR  [SS]    : d_r * inv_den per row
//   dsI  [SS]    : d_i * inv_den per row

__global__ __launch_bounds__(TPB, 1)
void bk_green_kernel(const float* __restrict__ he,
                     const float* __restrict__ h0d,
                     const float* __restrict__ h0s,
                     const float* __restrict__ h0p,
                     float* __restrict__ out,
                     int Brows)
{
    extern __shared__ float sm[];
    float* aBuf = sm;
    float* phiR = sm + NN * SS;
    float* phiI = phiR + NN * SS;
    float* dsR  = phiI + NN * SS;
    float* dsI  = dsR + SS;
    __shared__ float bcBuf[NN - 1];

    const int t = threadIdx.x;
    const int rowBase = blockIdx.x * TPB;
    const int rows = min(TPB, Brows - rowBase);

    // bc[k] = h0_super[k] * h0_sub[k] (shared across all rows)
    if (t < NN - 1) bcBuf[t] = h0s[t] * h0p[t];

    // Coalesced staging: a[row][j] = he[row][j] + h0_diag[j], transposed into smem.
    for (int i = t; i < rows * NN; i += TPB) {
        int row = i / NN;
        int j = i - row * NN;
        aBuf[j * SS + row] = he[(size_t)rowBase * NN + i] + __ldg(&h0d[j]);
    }
    __syncthreads();

    if (t < rows) {
        // ---- Pass 1: reverse continuant phi_rev[0..79] into smem ----
        float pr = 1.0f, pi = 0.0f;
        float cr = aBuf[(NN - 1) * SS + t];
        float ci = -1.0f;
        phiR[0 * SS + t] = 1.0f; phiI[0 * SS + t] = 0.0f;
        phiR[1 * SS + t] = cr;   phiI[1 * SS + t] = ci;
        #pragma unroll
        for (int k = 1; k <= NN - 2; k++) {
            float ak = aBuf[(NN - 1 - k) * SS + t];
            float bk = bcBuf[NN - 1 - k];
            float nr = ak * cr + ci - bk * pr;
            float ni = ak * ci - cr - bk * pi;
            phiR[(k + 1) * SS + t] = nr;
            phiI[(k + 1) * SS + t] = ni;
            pr = cr; pi = ci; cr = nr; ci = ni;
        }

        // ---- Pass 2: forward continuant theta; num[k] = theta_k * phi_rev[79-k]
        //      overwrites the phi slot it reads (slot used exactly once). ----
        pr = 1.0f; pi = 0.0f;
        cr = aBuf[0 * SS + t];   // theta_1
        ci = -1.0f;
        // num[0] = theta_0 * phi_rev[79] = phi_rev[79]: already in place.
        #pragma unroll
        for (int k = 1; k <= NN - 1; k++) {
            int slot = (NN - 1 - k) * SS + t;
            float qr = phiR[slot], qi = phiI[slot];
            phiR[slot] = cr * qr - ci * qi;   // num_r[k]
            phiI[slot] = cr * qi + ci * qr;   // num_i[k]
            float ak = aBuf[k * SS + t];
            float bk = bcBuf[k - 1];
            float nr = ak * cr + ci - bk * pr;
            float ni = ak * ci - cr - bk * pi;
            pr = cr; pi = ci; cr = nr; ci = ni;
        }
        // (cr, ci) = theta_N = denominator
        float inv = 1.0f / (cr * cr + ci * ci);
        dsR[t] = cr * inv;
        dsI[t] = ci * inv;
    }
    __syncthreads();

    // ---- Coalesced output: out[row][j] = num[j] * (dsR - i*dsI)  (float2) ----
    float2* out2 = (float2*)out;
    for (int i = t; i < rows * NN; i += TPB) {
        int row = i / NN;
        int j = i - row * NN;
        int slot = (NN - 1 - j) * SS + row;
        float nr = phiR[slot], ni = phiI[slot];
        float dr = dsR[row], di = dsI[row];
        float2 g;
        g.x = nr * dr + ni * di;
        g.y = ni * dr - nr * di;
        out2[(size_t)rowBase * NN + i] = g;
    }
}

extern "C" void kernel_launch(void* const* d_in, const int* in_sizes, int n_in,
                              void* d_out, int out_size)
{
    const float* he  = (const float*)d_in[0];   // he_diag (B*N)
    const float* h0d = (const float*)d_in[1];   // h0_diag (N)
    const float* h0s = (const float*)d_in[2];   // h0_sub  (N-1)
    const float* h0p = (const float*)d_in[3];   // h0_super(N-1)

    int Brows = in_sizes[0] / NN;
    size_t smem = (size_t)(3 * NN * SS + 2 * SS) * sizeof(float);  // 219,736 B

    cudaFuncSetAttribute(bk_green_kernel,
                         cudaFuncAttributeMaxDynamicSharedMemorySize, (int)smem);

    int grid = (Brows + TPB - 1) / TPB;
    bk_green_kernel<<<grid, TPB, smem>>>(he, h0d, h0s, h0p, (float*)d_out, Brows);
}

// round 2
// speedup vs baseline: 1.0362x; 1.0362x over previous
#include <cuda_runtime.h>

#define NN   80          // N (row length)
#define TPB  128         // threads per block
#define RPB  112         // rows per block (compute threads)
#define SS   113         // smem stride: 113 % 32 == 17 (odd -> conflict-free)

// dynamic smem layout (floats):
//   aBuf [NN*SS] : a[j] per row (transposed: [j*SS + rowLocal])
//   phiR [NN*SS] : phi_rev real -> overwritten with num real
//   phiI [NN*SS] : phi_rev imag -> overwritten with num imag
//   dsR  [SS]    : d_r * inv_den per row
//   dsI  [SS]    : d_i * inv_den per row
// total = (3*80*113 + 2*113)*4 = 109,312 B  -> 2 CTAs/SM

__global__ __launch_bounds__(TPB, 2)
void bk_green_kernel(const float* __restrict__ he,
                     const float* __restrict__ h0d,
                     const float* __restrict__ h0s,
                     const float* __restrict__ h0p,
                     float* __restrict__ out,
                     int Brows)
{
    extern __shared__ float sm[];
    float* aBuf = sm;
    float* phiR = sm + NN * SS;
    float* phiI = phiR + NN * SS;
    float* dsR  = phiI + NN * SS;
    float* dsI  = dsR + SS;
    __shared__ float bcBuf[NN - 1];

    const int t = threadIdx.x;
    const int rowBase = blockIdx.x * RPB;
    const int rows = min(RPB, Brows - rowBase);

    // bc[k] = h0_super[k] * h0_sub[k] (shared across all rows)
    if (t < NN - 1) bcBuf[t] = h0s[t] * h0p[t];

    // Coalesced staging: a[row][j] = he[row][j] + h0_diag[j], transposed into smem.
    for (int i = t; i < rows * NN; i += TPB) {
        int row = i / NN;
        int j = i - row * NN;
        aBuf[j * SS + row] = he[(size_t)rowBase * NN + i] + __ldg(&h0d[j]);
    }
    __syncthreads();

    if (t < rows) {
        // ---- Pass 1: reverse continuant phi_rev[0..79] into smem ----
        float pr = 1.0f, pi = 0.0f;
        float cr = aBuf[(NN - 1) * SS + t];
        float ci = -1.0f;
        phiR[0 * SS + t] = 1.0f; phiI[0 * SS + t] = 0.0f;
        phiR[1 * SS + t] = cr;   phiI[1 * SS + t] = ci;
        #pragma unroll 4
        for (int k = 1; k <= NN - 2; k++) {
            float ak = aBuf[(NN - 1 - k) * SS + t];
            float bk = bcBuf[NN - 1 - k];
            float nr = ak * cr + ci - bk * pr;
            float ni = ak * ci - cr - bk * pi;
            phiR[(k + 1) * SS + t] = nr;
            phiI[(k + 1) * SS + t] = ni;
            pr = cr; pi = ci; cr = nr; ci = ni;
        }

        // ---- Pass 2: forward continuant theta; num[k] = theta_k * phi_rev[79-k]
        //      overwrites the phi slot it reads (slot used exactly once). ----
        pr = 1.0f; pi = 0.0f;
        cr = aBuf[0 * SS + t];   // theta_1
        ci = -1.0f;
        // num[0] = theta_0 * phi_rev[79] = phi_rev[79]: already in place.
        #pragma unroll 4
        for (int k = 1; k <= NN - 1; k++) {
            int slot = (NN - 1 - k) * SS + t;
            float qr = phiR[slot], qi = phiI[slot];
            phiR[slot] = cr * qr - ci * qi;   // num_r[k]
            phiI[slot] = cr * qi + ci * qr;   // num_i[k]
            float ak = aBuf[k * SS + t];
            float bk = bcBuf[k - 1];
            float nr = ak * cr + ci - bk * pr;
            float ni = ak * ci - cr - bk * pi;
            pr = cr; pi = ci; cr = nr; ci = ni;
        }
        // (cr, ci) = theta_N = denominator
        float inv = 1.0f / (cr * cr + ci * ci);
        dsR[t] = cr * inv;
        dsI[t] = ci * inv;
    }
    __syncthreads();

    // ---- Coalesced output: out[row][j] = num[j] * (dsR - i*dsI)  (float2) ----
    float2* out2 = (float2*)out;
    for (int i = t; i < rows * NN; i += TPB) {
        int row = i / NN;
        int j = i - row * NN;
        int slot = (NN - 1 - j) * SS + row;
        float nr = phiR[slot], ni = phiI[slot];
        float dr = dsR[row], di = dsI[row];
        float2 g;
        g.x = nr * dr + ni * di;
        g.y = ni * dr - nr * di;
        out2[(size_t)rowBase * NN + i] = g;
    }
}

extern "C" void kernel_launch(void* const* d_in, const int* in_sizes, int n_in,
                              void* d_out, int out_size)
{
    const float* he  = (const float*)d_in[0];   // he_diag (B*N)
    const float* h0d = (const float*)d_in[1];   // h0_diag (N)
    const float* h0s = (const float*)d_in[2];   // h0_sub  (N-1)
    const float* h0p = (const float*)d_in[3];   // h0_super(N-1)

    int Brows = in_sizes[0] / NN;
    size_t smem = (size_t)(3 * NN * SS + 2 * SS) * sizeof(float);  // 109,312 B

    cudaFuncSetAttribute(bk_green_kernel,
                         cudaFuncAttributeMaxDynamicSharedMemorySize, (int)smem);

    int grid = (Brows + RPB - 1) / RPB;
    bk_green_kernel<<<grid, TPB, smem>>>(he, h0d, h0s, h0p, (float*)d_out, Brows);
}